// round 1
// baseline (speedup 1.0000x reference)
#include <cuda_runtime.h>
#include <math.h>

#define B_ 32
#define C_ 256
#define L_ 4096
#define H_ (2*C_)
#define BL_ (B_*L_)

// ---------------- scratch (device globals; no allocation allowed) ----------
__device__ float g_y1[(size_t)B_*C_*L_];   // conv1 output [B,C,L]
__device__ float g_xp[(size_t)B_*L_*C_];   // conv2 output transposed [B,L,C]
__device__ float g_t1[(size_t)B_*L_*C_];   // freq / sd / fw  [B*L, C]
__device__ float g_h [(size_t)B_*L_*H_];   // hidden [B*L, 2C]
__device__ float g_dct [C_*C_];            // [n][k] = Dm[k][n]
__device__ float g_fc1t[C_*H_];            // [c][j] = fc1_w[j][c]
__device__ float g_fc2t[H_*C_];            // [j][c] = fc2_w[c][j]

// ---------------- precompute: DCT matrix + transposed fc weights -----------
__global__ void precompute_kernel(const float* __restrict__ fc1_w,
                                  const float* __restrict__ fc2_w) {
    int idx = blockIdx.x * blockDim.x + threadIdx.x;
    if (idx < C_*C_) {
        int n = idx / C_, k = idx % C_;
        double v = 2.0 * cos(M_PI * (double)k * (2.0*n + 1.0) / (2.0 * C_));
        g_dct[n*C_ + k] = (float)v;
    }
    if (idx < C_*H_) {
        int c = idx / H_, j = idx % H_;
        g_fc1t[c*H_ + j] = fc1_w[j*C_ + c];   // fc1_w: [2C, C]
        g_fc2t[j*C_ + c] = fc2_w[c*H_ + j];   // fc2_w: [C, 2C]
    }
}

// ---------------- conv1d(K=3,pad=1) + eval-BN (+relu), optional transpose --
#define CONV_BCO 64
#define CONV_BL  64
#define CONV_CIK 16

__global__ void conv_bn_kernel(const float* __restrict__ x,
                               const float* __restrict__ w,
                               const float* __restrict__ bng, const float* __restrict__ bnb,
                               const float* __restrict__ bnm, const float* __restrict__ bnv,
                               float* __restrict__ y, int do_relu, int transpose_out) {
    __shared__ float xs[CONV_CIK][CONV_BL + 2];
    __shared__ float ws[CONV_CIK][CONV_BCO][3];
    int b   = blockIdx.z;
    int co0 = blockIdx.y * CONV_BCO;
    int l0  = blockIdx.x * CONV_BL;
    int tid = threadIdx.x;            // 256 threads
    int tx = tid & 15, ty = tid >> 4; // 16x16, each 4co x 4l
    float acc[4][4] = {};
    const float* xb = x + (size_t)b * C_ * L_;

    for (int ci0 = 0; ci0 < C_; ci0 += CONV_CIK) {
        for (int i = tid; i < CONV_CIK*(CONV_BL+2); i += 256) {
            int r = i / (CONV_BL+2), cc = i % (CONV_BL+2);
            int gl = l0 + cc - 1;
            xs[r][cc] = (gl >= 0 && gl < L_) ? xb[(size_t)(ci0 + r)*L_ + gl] : 0.f;
        }
        for (int i = tid; i < CONV_CIK*CONV_BCO*3; i += 256) {
            int k = i % 3; int rest = i / 3;
            int ci = rest % CONV_CIK; int co = rest / CONV_CIK;
            ws[ci][co][k] = w[(size_t)(co0+co)*C_*3 + (size_t)(ci0+ci)*3 + k];
        }
        __syncthreads();
        #pragma unroll
        for (int i = 0; i < CONV_CIK; i++) {
            float xv[6];
            #pragma unroll
            for (int j = 0; j < 6; j++) xv[j] = xs[i][tx*4 + j];
            #pragma unroll
            for (int m = 0; m < 4; m++) {
                float w0 = ws[i][ty*4+m][0];
                float w1 = ws[i][ty*4+m][1];
                float w2 = ws[i][ty*4+m][2];
                #pragma unroll
                for (int n = 0; n < 4; n++)
                    acc[m][n] += w0*xv[n] + w1*xv[n+1] + w2*xv[n+2];
            }
        }
        __syncthreads();
    }
    #pragma unroll
    for (int m = 0; m < 4; m++) {
        int co = co0 + ty*4 + m;
        float scale = bng[co] * rsqrtf(bnv[co] + 1e-5f);
        float shift = bnb[co] - bnm[co]*scale;
        #pragma unroll
        for (int n = 0; n < 4; n++) {
            float v = acc[m][n]*scale + shift;
            if (do_relu) v = fmaxf(v, 0.f);
            int l = l0 + tx*4 + n;
            if (transpose_out) y[((size_t)b*L_ + l)*C_ + co] = v;
            else               y[((size_t)b*C_ + co)*L_ + l] = v;
        }
    }
}

// ---------------- SGEMM 128x128x8, 8x8 per thread, fused epilogue ----------
// C[M,N] = A[M,K] @ B[K,N]; M%128==0, N%128==0, K%8==0
#define GM 128
#define GN 128
#define GK 8

__global__ void sgemm_kernel(const float* __restrict__ A, const float* __restrict__ B,
                             float* __restrict__ C, int M, int N, int K, int epi) {
    __shared__ float As[GK][GM];
    __shared__ float Bs[GK][GN];
    int tid = threadIdx.x;            // 256
    size_t m0 = (size_t)blockIdx.y * GM;
    size_t n0 = (size_t)blockIdx.x * GN;
    int tx = tid & 15, ty = tid >> 4;

    float acc[8][8] = {};
    int a_row = tid >> 1;
    int a_col = (tid & 1) * 4;
    int b_row = tid >> 5;
    int b_col = (tid & 31) * 4;

    for (int k0 = 0; k0 < K; k0 += GK) {
        float4 av = *(const float4*)&A[(m0 + a_row)*K + k0 + a_col];
        As[a_col+0][a_row] = av.x;
        As[a_col+1][a_row] = av.y;
        As[a_col+2][a_row] = av.z;
        As[a_col+3][a_row] = av.w;
        *(float4*)&Bs[b_row][b_col] = *(const float4*)&B[(size_t)(k0 + b_row)*N + n0 + b_col];
        __syncthreads();
        #pragma unroll
        for (int kk = 0; kk < GK; kk++) {
            float ar[8], br[8];
            *(float4*)&ar[0] = *(const float4*)&As[kk][ty*8];
            *(float4*)&ar[4] = *(const float4*)&As[kk][ty*8+4];
            *(float4*)&br[0] = *(const float4*)&Bs[kk][tx*8];
            *(float4*)&br[4] = *(const float4*)&Bs[kk][tx*8+4];
            #pragma unroll
            for (int i = 0; i < 8; i++)
                #pragma unroll
                for (int j = 0; j < 8; j++)
                    acc[i][j] += ar[i]*br[j];
        }
        __syncthreads();
    }
    #pragma unroll
    for (int i = 0; i < 8; i++) {
        size_t row = m0 + ty*8 + i;
        #pragma unroll
        for (int j0 = 0; j0 < 8; j0 += 4) {
            float4 v;
            float t[4];
            #pragma unroll
            for (int j = 0; j < 4; j++) {
                float u = acc[i][j0+j];
                if (epi == 1) u = fmaxf(u, 0.f);
                else if (epi == 2) u = 1.f/(1.f + expf(-u));
                t[j] = u;
            }
            v.x = t[0]; v.y = t[1]; v.z = t[2]; v.w = t[3];
            *(float4*)&C[row*N + n0 + tx*8 + j0] = v;
        }
    }
}

// ---------------- LayerNorm over last dim (C_=256), in-place ---------------
__global__ void ln_kernel(float* __restrict__ data,
                          const float* __restrict__ g, const float* __restrict__ b) {
    __shared__ float sh[8];
    size_t row = blockIdx.x;
    float* p = data + row * C_;
    int t = threadIdx.x;      // 256
    int lane = t & 31, wid = t >> 5;
    float v = p[t];

    float s = v;
    #pragma unroll
    for (int o = 16; o; o >>= 1) s += __shfl_xor_sync(0xffffffffu, s, o);
    if (lane == 0) sh[wid] = s;
    __syncthreads();
    if (wid == 0) {
        float r = (lane < 8) ? sh[lane] : 0.f;
        #pragma unroll
        for (int o = 4; o; o >>= 1) r += __shfl_xor_sync(0xffffffffu, r, o);
        if (lane == 0) sh[0] = r;
    }
    __syncthreads();
    float mean = sh[0] * (1.f / C_);
    __syncthreads();

    float d = v - mean;
    float s2 = d * d;
    #pragma unroll
    for (int o = 16; o; o >>= 1) s2 += __shfl_xor_sync(0xffffffffu, s2, o);
    if (lane == 0) sh[wid] = s2;
    __syncthreads();
    if (wid == 0) {
        float r = (lane < 8) ? sh[lane] : 0.f;
        #pragma unroll
        for (int o = 4; o; o >>= 1) r += __shfl_xor_sync(0xffffffffu, r, o);
        if (lane == 0) sh[0] = r;
    }
    __syncthreads();
    float var = sh[0] * (1.f / C_);
    p[t] = d * rsqrtf(var + 1e-6f) * g[t] + b[t];
}

// ------- final: out[b,c,l] = relu(xp[b,l,c]*fw[b,l,c] + x[b,c,l]) ----------
__global__ void final_kernel(const float* __restrict__ xp, const float* __restrict__ fw,
                             const float* __restrict__ x, float* __restrict__ out) {
    __shared__ float tile[32][33];
    int b  = blockIdx.z;
    int c0 = blockIdx.x * 32;
    int l0 = blockIdx.y * 32;
    int tx = threadIdx.x, ty = threadIdx.y;   // 32 x 8
    #pragma unroll
    for (int i = 0; i < 32; i += 8) {
        int l = l0 + ty + i;
        size_t idx = ((size_t)b*L_ + l)*C_ + c0 + tx;
        tile[ty+i][tx] = xp[idx] * fw[idx];
    }
    __syncthreads();
    #pragma unroll
    for (int i = 0; i < 32; i += 8) {
        int c = c0 + ty + i;
        int l = l0 + tx;
        size_t idx = ((size_t)b*C_ + c)*L_ + l;
        out[idx] = fmaxf(tile[tx][ty+i] + x[idx], 0.f);
    }
}

// ---------------------------------------------------------------------------
extern "C" void kernel_launch(void* const* d_in, const int* in_sizes, int n_in,
                              void* d_out, int out_size) {
    const float* x       = (const float*)d_in[0];
    const float* conv1_w = (const float*)d_in[1];
    const float* bn1_g   = (const float*)d_in[2];
    const float* bn1_b   = (const float*)d_in[3];
    const float* bn1_m   = (const float*)d_in[4];
    const float* bn1_v   = (const float*)d_in[5];
    const float* conv2_w = (const float*)d_in[6];
    const float* bn2_g   = (const float*)d_in[7];
    const float* bn2_b   = (const float*)d_in[8];
    const float* bn2_m   = (const float*)d_in[9];
    const float* bn2_v   = (const float*)d_in[10];
    const float* fc1_w   = (const float*)d_in[11];
    const float* fc2_w   = (const float*)d_in[12];
    const float* ln_g    = (const float*)d_in[13];
    const float* ln_b    = (const float*)d_in[14];
    float* out = (float*)d_out;

    float *y1, *xp, *t1, *h, *dct, *fc1t, *fc2t;
    cudaGetSymbolAddress((void**)&y1,   g_y1);
    cudaGetSymbolAddress((void**)&xp,   g_xp);
    cudaGetSymbolAddress((void**)&t1,   g_t1);
    cudaGetSymbolAddress((void**)&h,    g_h);
    cudaGetSymbolAddress((void**)&dct,  g_dct);
    cudaGetSymbolAddress((void**)&fc1t, g_fc1t);
    cudaGetSymbolAddress((void**)&fc2t, g_fc2t);

    // 0. precompute DCT matrix + transposed weights
    precompute_kernel<<<(C_*H_ + 255)/256, 256>>>(fc1_w, fc2_w);

    // 1. conv1 + bn1 + relu  -> y1 [B,C,L]
    {
        dim3 grid(L_/CONV_BL, C_/CONV_BCO, B_);
        conv_bn_kernel<<<grid, 256>>>(x, conv1_w, bn1_g, bn1_b, bn1_m, bn1_v,
                                      y1, /*relu=*/1, /*transpose=*/0);
    }
    // 2. conv2 + bn2 -> xp [B,L,C] (transposed)
    {
        dim3 grid(L_/CONV_BL, C_/CONV_BCO, B_);
        conv_bn_kernel<<<grid, 256>>>(y1, conv2_w, bn2_g, bn2_b, bn2_m, bn2_v,
                                      xp, /*relu=*/0, /*transpose=*/1);
    }
    // 3. freq = xp @ Dm^T  -> t1 [BL, C]
    {
        dim3 grid(C_/GN, BL_/GM);
        sgemm_kernel<<<grid, 256>>>(xp, dct, t1, BL_, C_, C_, /*epi=*/0);
    }
    // 4. sd = LN(freq), in place
    ln_kernel<<<BL_, C_>>>(t1, ln_g, ln_b);

    // 5. h = relu(sd @ fc1^T) -> g_h [BL, 2C]
    {
        dim3 grid(H_/GN, BL_/GM);
        sgemm_kernel<<<grid, 256>>>(t1, fc1t, h, BL_, H_, C_, /*epi=*/1);
    }
    // 6. fw = sigmoid(h @ fc2^T) -> t1 [BL, C]
    {
        dim3 grid(C_/GN, BL_/GM);
        sgemm_kernel<<<grid, 256>>>(h, fc2t, t1, BL_, C_, H_, /*epi=*/2);
    }
    // 7. fw = LN(fw), in place
    ln_kernel<<<BL_, C_>>>(t1, ln_g, ln_b);

    // 8. out = relu(transpose(xp * fw) + x)
    {
        dim3 grid(C_/32, L_/32, B_);
        final_kernel<<<grid, dim3(32, 8)>>>(xp, t1, x, out);
    }
}